// round 13
// baseline (speedup 1.0000x reference)
#include <cuda_runtime.h>
#include <math.h>

#define IN_DIM  2976
#define H1_DIM  5952
#define H2_DIM  1488
#define OUT_DIM 744
#define BATCH   8192

#define FEAT_F4 (OUT_DIM / 4)   // 186 float4 per feat row
#define N_HEAD  17              // 10 reg + 3 c1 + 4 c2
#define W_PAD_F4 192            // padded float4 per weight row (zero-filled tail)
#define HEAD_SMEM (N_HEAD * W_PAD_F4 * 16)   // 52224 bytes

typedef unsigned long long u64;

// ---------------------------------------------------------------------------
// packed f32x2 helpers (SASS FFMA2 — only reachable via PTX)
// ---------------------------------------------------------------------------
__device__ __forceinline__ u64 pfma(u64 a, u64 b, u64 c) {
    u64 r; asm("fma.rn.f32x2 %0, %1, %2, %3;" : "=l"(r) : "l"(a), "l"(b), "l"(c)); return r;
}
__device__ __forceinline__ u64 padd(u64 a, u64 b) {
    u64 r; asm("add.rn.f32x2 %0, %1, %2;" : "=l"(r) : "l"(a), "l"(b)); return r;
}
__device__ __forceinline__ void upk(u64 v, float& lo, float& hi) {
    asm("mov.b64 {%0,%1}, %2;" : "=f"(lo), "=f"(hi) : "l"(v));
}

__device__ __forceinline__ float lrelu(float v) {
    return fmaxf(v, 0.01f * v);
}
__device__ __forceinline__ float dot4(float4 a, float4 b) {
    return a.x * b.x + a.y * b.y + a.z * b.z + a.w * b.w;
}

// ---------------------------------------------------------------------------
// Kernel 1: fused block-diagonal sparse MLP -> feat[b, k]  (unchanged, ~28us)
// ---------------------------------------------------------------------------
template <int B_TILE>
__global__ __launch_bounds__(128)
void sparse_mlp_kernel(const float* __restrict__ x,
                       const float* __restrict__ W1,
                       const float* __restrict__ W2,
                       const float* __restrict__ W3,
                       float* __restrict__ feat)
{
    const int k = blockIdx.x * 128 + threadIdx.x;
    if (k >= OUT_DIM) return;

    float4 w1[8];
#pragma unroll
    for (int j = 0; j < 8; j++)
        w1[j] = *(const float4*)(W1 + (size_t)(8 * k + j) * IN_DIM + 4 * k);

    float w20[8], w21[8];
    {
        float4 q;
        q = *(const float4*)(W2 + (size_t)(2 * k + 0) * H1_DIM + 8 * k + 0);
        w20[0] = q.x; w20[1] = q.y; w20[2] = q.z; w20[3] = q.w;
        q = *(const float4*)(W2 + (size_t)(2 * k + 0) * H1_DIM + 8 * k + 4);
        w20[4] = q.x; w20[5] = q.y; w20[6] = q.z; w20[7] = q.w;
        q = *(const float4*)(W2 + (size_t)(2 * k + 1) * H1_DIM + 8 * k + 0);
        w21[0] = q.x; w21[1] = q.y; w21[2] = q.z; w21[3] = q.w;
        q = *(const float4*)(W2 + (size_t)(2 * k + 1) * H1_DIM + 8 * k + 4);
        w21[4] = q.x; w21[5] = q.y; w21[6] = q.z; w21[7] = q.w;
    }
    const float2 w3 = *(const float2*)(W3 + (size_t)k * H2_DIM + 2 * k);

    const int b0 = blockIdx.y * B_TILE;
    const float4* __restrict__ xr = (const float4*)x;

    constexpr int MLP = 4;
    static_assert(B_TILE % MLP == 0, "tile divisible by MLP");
    for (int g = 0; g < B_TILE / MLP; g++) {
        const int b = b0 + MLP * g;
        float4 xv[MLP];
#pragma unroll
        for (int t = 0; t < MLP; t++)
            xv[t] = __ldcs(xr + (size_t)(b + t) * (IN_DIM / 4) + k);

#pragma unroll
        for (int t = 0; t < MLP; t++) {
            float a0 = 0.f, a1 = 0.f;
#pragma unroll
            for (int j = 0; j < 8; j++) {
                const float v = lrelu(dot4(w1[j], xv[t]));
                a0 += w20[j] * v;
                a1 += w21[j] * v;
            }
            const float f = w3.x * lrelu(a0) + w3.y * lrelu(a1);
            feat[(size_t)(b + t) * OUT_DIM + k] = f;
        }
    }
}

// ---------------------------------------------------------------------------
// Kernel 2: heads. Weights staged in SMEM once per block (kills the 415 MB
// L1 weight re-read). Warp handles 2 rows; each weight LDS.128 feeds 4 FFMA2.
// acc packed f32x2 over the feature axis; butterfly reduce; lo+hi fold.
// ---------------------------------------------------------------------------
__global__ __launch_bounds__(256)
void head_kernel(const float* __restrict__ feat,
                 const float* __restrict__ wo1, const float* __restrict__ bo1,
                 const float* __restrict__ wo2, const float* __restrict__ bo2,
                 const float* __restrict__ wo3, const float* __restrict__ bo3,
                 float* __restrict__ out_reg,
                 float* __restrict__ out_c1,
                 float* __restrict__ out_c2)
{
    extern __shared__ __align__(16) float sw[];   // [N_HEAD][W_PAD_F4 * 4]
    const int tid = threadIdx.x;

    // stage head weights into smem (zero-padded tail => guard-free compute)
    for (int i = tid; i < N_HEAD * W_PAD_F4; i += 256) {
        const int o = i / W_PAD_F4;
        const int c = i - o * W_PAD_F4;
        float4 val = make_float4(0.f, 0.f, 0.f, 0.f);
        if (c < FEAT_F4) {
            const float* wrow = (o < 10) ? (wo2 + (size_t)o * OUT_DIM)
                              : (o < 13) ? (wo1 + (size_t)(o - 10) * OUT_DIM)
                                         : (wo3 + (size_t)(o - 13) * OUT_DIM);
            val = ((const float4*)wrow)[c];
        }
        ((float4*)sw)[i] = val;
    }
    __syncthreads();

    const int warp = tid >> 5;
    const int lane = tid & 31;
    const int r0 = (blockIdx.x * 8 + warp) * 2;      // 2 rows per warp
    if (r0 >= BATCH) return;

    const ulonglong2* __restrict__ fpa =
        (const ulonglong2*)(feat + (size_t)r0 * OUT_DIM);
    const ulonglong2* __restrict__ fpb =
        (const ulonglong2*)(feat + (size_t)(r0 + 1) * OUT_DIM);
    const ulonglong2* __restrict__ swp = (const ulonglong2*)sw;

    u64 accA[N_HEAD], accB[N_HEAD];
#pragma unroll
    for (int o = 0; o < N_HEAD; o++) { accA[o] = 0ULL; accB[o] = 0ULL; }

#pragma unroll
    for (int v = 0; v < 6; v++) {
        const int idx = v * 32 + lane;
        ulonglong2 xa, xb;
        if (idx < FEAT_F4) { xa = fpa[idx]; xb = fpb[idx]; }
        else { xa.x = xa.y = 0ULL; xb.x = xb.y = 0ULL; }
#pragma unroll
        for (int o = 0; o < N_HEAD; o++) {
            const ulonglong2 w = swp[o * W_PAD_F4 + idx];   // LDS.128, conflict-free
            accA[o] = pfma(w.x, xa.x, accA[o]);
            accA[o] = pfma(w.y, xa.y, accA[o]);
            accB[o] = pfma(w.x, xb.x, accB[o]);
            accB[o] = pfma(w.y, xb.y, accB[o]);
        }
    }

    // butterfly reduce (packed): all lanes end with full sums
#pragma unroll
    for (int o = 0; o < N_HEAD; o++) {
#pragma unroll
        for (int s = 16; s > 0; s >>= 1) {
            accA[o] = padd(accA[o], __shfl_xor_sync(0xffffffffu, accA[o], s));
            accB[o] = padd(accB[o], __shfl_xor_sync(0xffffffffu, accB[o], s));
        }
    }

    if (lane < 2) {
        const int r = r0 + lane;
        float res[N_HEAD];
#pragma unroll
        for (int o = 0; o < N_HEAD; o++) {
            float lo, hi;
            upk((lane == 0) ? accA[o] : accB[o], lo, hi);
            res[o] = lo + hi;
        }

#pragma unroll
        for (int o = 0; o < 10; o++)
            out_reg[(size_t)r * 10 + o] = lrelu(res[o] + bo2[o]);

        {
            float z0 = lrelu(res[10] + bo1[0]);
            float z1 = lrelu(res[11] + bo1[1]);
            float z2 = lrelu(res[12] + bo1[2]);
            float m = fmaxf(z0, fmaxf(z1, z2));
            float e0 = __expf(z0 - m), e1 = __expf(z1 - m), e2 = __expf(z2 - m);
            float inv = 1.f / (e0 + e1 + e2);
            out_c1[(size_t)r * 3 + 0] = e0 * inv;
            out_c1[(size_t)r * 3 + 1] = e1 * inv;
            out_c1[(size_t)r * 3 + 2] = e2 * inv;
        }
        {
            float z0 = lrelu(res[13] + bo3[0]);
            float z1 = lrelu(res[14] + bo3[1]);
            float z2 = lrelu(res[15] + bo3[2]);
            float z3 = lrelu(res[16] + bo3[3]);
            float m = fmaxf(fmaxf(z0, z1), fmaxf(z2, z3));
            float e0 = __expf(z0 - m), e1 = __expf(z1 - m);
            float e2 = __expf(z2 - m), e3 = __expf(z3 - m);
            float inv = 1.f / (e0 + e1 + e2 + e3);
            out_c2[(size_t)r * 4 + 0] = e0 * inv;
            out_c2[(size_t)r * 4 + 1] = e1 * inv;
            out_c2[(size_t)r * 4 + 2] = e2 * inv;
            out_c2[(size_t)r * 4 + 3] = e3 * inv;
        }
    }
}

// ---------------------------------------------------------------------------
// launch
// ---------------------------------------------------------------------------
extern "C" void kernel_launch(void* const* d_in, const int* in_sizes, int n_in,
                              void* d_out, int out_size)
{
    // metadata order: x, W1, W2, W3, m1, m2, m3, wo1, bo1, wo2, bo2, wo3, bo3
    const float* x   = (const float*)d_in[0];
    const float* W1  = (const float*)d_in[1];
    const float* W2  = (const float*)d_in[2];
    const float* W3  = (const float*)d_in[3];
    const float* wo1 = (const float*)d_in[7];
    const float* bo1 = (const float*)d_in[8];
    const float* wo2 = (const float*)d_in[9];
    const float* bo2 = (const float*)d_in[10];
    const float* wo3 = (const float*)d_in[11];
    const float* bo3 = (const float*)d_in[12];

    float* out = (float*)d_out;
    // output layout: reg [B,10], c1 [B,3], c2 [B,4], feat [B,744]
    float* out_reg  = out;
    float* out_c1   = out + (size_t)BATCH * 10;
    float* out_c2   = out + (size_t)BATCH * 13;
    float* out_feat = out + (size_t)BATCH * 17;

    constexpr int B_TILE = 16;                 // 8192 / 16 = 512 exactly
    static_assert(BATCH % B_TILE == 0, "B_TILE must divide BATCH");
    dim3 grid1((OUT_DIM + 127) / 128, BATCH / B_TILE);   // (6, 512)
    sparse_mlp_kernel<B_TILE><<<grid1, 128>>>(x, W1, W2, W3, out_feat);

    // head: 52 KB dynamic smem (> 48 KB static limit) — opt in once
    static bool attr_set = false;
    if (!attr_set) {
        cudaFuncSetAttribute(head_kernel,
                             cudaFuncAttributeMaxDynamicSharedMemorySize,
                             HEAD_SMEM);
        attr_set = true;
    }
    const int blocks2 = BATCH / 16;    // 2 rows/warp, 8 warps/block -> 512 blocks
    head_kernel<<<blocks2, 256, HEAD_SMEM>>>(out_feat, wo1, bo1, wo2, bo2,
                                             wo3, bo3, out_reg, out_c1, out_c2);
}

// round 14
// speedup vs baseline: 1.0722x; 1.0722x over previous
#include <cuda_runtime.h>
#include <math.h>

#define IN_DIM  2976
#define H1_DIM  5952
#define H2_DIM  1488
#define OUT_DIM 744
#define BATCH   8192

#define FEAT_F4 (OUT_DIM / 4)   // 186 float4 per feat row
#define N_HEAD  17              // 10 reg + 3 c1 + 4 c2
#define W_PAD_F4 192            // padded float4 per weight row (zero-filled tail)
#define HEAD_SMEM (N_HEAD * W_PAD_F4 * 16)   // 52224 bytes

__device__ __forceinline__ float lrelu(float v) {
    return fmaxf(v, 0.01f * v);
}
__device__ __forceinline__ float dot4(float4 a, float4 b) {
    return a.x * b.x + a.y * b.y + a.z * b.z + a.w * b.w;
}

// ---------------------------------------------------------------------------
// Kernel 1: fused block-diagonal sparse MLP -> feat[b, k]  (unchanged, ~28us)
// ---------------------------------------------------------------------------
template <int B_TILE>
__global__ __launch_bounds__(128)
void sparse_mlp_kernel(const float* __restrict__ x,
                       const float* __restrict__ W1,
                       const float* __restrict__ W2,
                       const float* __restrict__ W3,
                       float* __restrict__ feat)
{
    const int k = blockIdx.x * 128 + threadIdx.x;
    if (k >= OUT_DIM) return;

    float4 w1[8];
#pragma unroll
    for (int j = 0; j < 8; j++)
        w1[j] = *(const float4*)(W1 + (size_t)(8 * k + j) * IN_DIM + 4 * k);

    float w20[8], w21[8];
    {
        float4 q;
        q = *(const float4*)(W2 + (size_t)(2 * k + 0) * H1_DIM + 8 * k + 0);
        w20[0] = q.x; w20[1] = q.y; w20[2] = q.z; w20[3] = q.w;
        q = *(const float4*)(W2 + (size_t)(2 * k + 0) * H1_DIM + 8 * k + 4);
        w20[4] = q.x; w20[5] = q.y; w20[6] = q.z; w20[7] = q.w;
        q = *(const float4*)(W2 + (size_t)(2 * k + 1) * H1_DIM + 8 * k + 0);
        w21[0] = q.x; w21[1] = q.y; w21[2] = q.z; w21[3] = q.w;
        q = *(const float4*)(W2 + (size_t)(2 * k + 1) * H1_DIM + 8 * k + 4);
        w21[4] = q.x; w21[5] = q.y; w21[6] = q.z; w21[7] = q.w;
    }
    const float2 w3 = *(const float2*)(W3 + (size_t)k * H2_DIM + 2 * k);

    const int b0 = blockIdx.y * B_TILE;
    const float4* __restrict__ xr = (const float4*)x;

    constexpr int MLP = 4;
    static_assert(B_TILE % MLP == 0, "tile divisible by MLP");
    for (int g = 0; g < B_TILE / MLP; g++) {
        const int b = b0 + MLP * g;
        float4 xv[MLP];
#pragma unroll
        for (int t = 0; t < MLP; t++)
            xv[t] = __ldcs(xr + (size_t)(b + t) * (IN_DIM / 4) + k);

#pragma unroll
        for (int t = 0; t < MLP; t++) {
            float a0 = 0.f, a1 = 0.f;
#pragma unroll
            for (int j = 0; j < 8; j++) {
                const float v = lrelu(dot4(w1[j], xv[t]));
                a0 += w20[j] * v;
                a1 += w21[j] * v;
            }
            const float f = w3.x * lrelu(a0) + w3.y * lrelu(a1);
            feat[(size_t)(b + t) * OUT_DIM + k] = f;
        }
    }
}

// ---------------------------------------------------------------------------
// Kernel 2: heads. Weights staged in SMEM once per block. Warp handles 2 rows.
// SCALAR f32 accumulators (34 regs, not 68 packed) + no feat preload =>
// ~60 regs => 3 blocks/SM => 24 warps/SM (vs 8 in R13). Loads stay 128-bit.
// ---------------------------------------------------------------------------
__global__ __launch_bounds__(256, 3)
void head_kernel(const float* __restrict__ feat,
                 const float* __restrict__ wo1, const float* __restrict__ bo1,
                 const float* __restrict__ wo2, const float* __restrict__ bo2,
                 const float* __restrict__ wo3, const float* __restrict__ bo3,
                 float* __restrict__ out_reg,
                 float* __restrict__ out_c1,
                 float* __restrict__ out_c2)
{
    extern __shared__ __align__(16) float sw[];   // [N_HEAD][W_PAD_F4 * 4]
    const int tid = threadIdx.x;

    // stage head weights into smem (zero-padded tail => guard-free compute)
    for (int i = tid; i < N_HEAD * W_PAD_F4; i += 256) {
        const int o = i / W_PAD_F4;
        const int c = i - o * W_PAD_F4;
        float4 val = make_float4(0.f, 0.f, 0.f, 0.f);
        if (c < FEAT_F4) {
            const float* wrow = (o < 10) ? (wo2 + (size_t)o * OUT_DIM)
                              : (o < 13) ? (wo1 + (size_t)(o - 10) * OUT_DIM)
                                         : (wo3 + (size_t)(o - 13) * OUT_DIM);
            val = ((const float4*)wrow)[c];
        }
        ((float4*)sw)[i] = val;
    }
    __syncthreads();

    const int warp = tid >> 5;
    const int lane = tid & 31;
    const int r0 = (blockIdx.x * 8 + warp) * 2;      // 2 rows per warp
    if (r0 >= BATCH) return;

    const float4* __restrict__ fpa = (const float4*)(feat + (size_t)r0 * OUT_DIM);
    const float4* __restrict__ fpb = (const float4*)(feat + (size_t)(r0 + 1) * OUT_DIM);
    const float4* __restrict__ swp = (const float4*)sw;

    float accA[N_HEAD], accB[N_HEAD];
#pragma unroll
    for (int o = 0; o < N_HEAD; o++) { accA[o] = 0.f; accB[o] = 0.f; }

#pragma unroll
    for (int v = 0; v < 6; v++) {
        const int idx = v * 32 + lane;
        float4 fa, fb;
        if (idx < FEAT_F4) { fa = fpa[idx]; fb = fpb[idx]; }
        else { fa = make_float4(0.f, 0.f, 0.f, 0.f); fb = fa; }
#pragma unroll
        for (int o = 0; o < N_HEAD; o++) {
            const float4 w = swp[o * W_PAD_F4 + idx];   // LDS.128, conflict-free
            accA[o] += dot4(w, fa);
            accB[o] += dot4(w, fb);
        }
    }

    // butterfly reduce: all lanes end with full sums
#pragma unroll
    for (int o = 0; o < N_HEAD; o++) {
#pragma unroll
        for (int s = 16; s > 0; s >>= 1) {
            accA[o] += __shfl_xor_sync(0xffffffffu, accA[o], s);
            accB[o] += __shfl_xor_sync(0xffffffffu, accB[o], s);
        }
    }

    if (lane < 2) {
        const int r = r0 + lane;
        float res[N_HEAD];
#pragma unroll
        for (int o = 0; o < N_HEAD; o++)
            res[o] = (lane == 0) ? accA[o] : accB[o];

#pragma unroll
        for (int o = 0; o < 10; o++)
            out_reg[(size_t)r * 10 + o] = lrelu(res[o] + bo2[o]);

        {
            float z0 = lrelu(res[10] + bo1[0]);
            float z1 = lrelu(res[11] + bo1[1]);
            float z2 = lrelu(res[12] + bo1[2]);
            float m = fmaxf(z0, fmaxf(z1, z2));
            float e0 = __expf(z0 - m), e1 = __expf(z1 - m), e2 = __expf(z2 - m);
            float inv = 1.f / (e0 + e1 + e2);
            out_c1[(size_t)r * 3 + 0] = e0 * inv;
            out_c1[(size_t)r * 3 + 1] = e1 * inv;
            out_c1[(size_t)r * 3 + 2] = e2 * inv;
        }
        {
            float z0 = lrelu(res[13] + bo3[0]);
            float z1 = lrelu(res[14] + bo3[1]);
            float z2 = lrelu(res[15] + bo3[2]);
            float z3 = lrelu(res[16] + bo3[3]);
            float m = fmaxf(fmaxf(z0, z1), fmaxf(z2, z3));
            float e0 = __expf(z0 - m), e1 = __expf(z1 - m);
            float e2 = __expf(z2 - m), e3 = __expf(z3 - m);
            float inv = 1.f / (e0 + e1 + e2 + e3);
            out_c2[(size_t)r * 4 + 0] = e0 * inv;
            out_c2[(size_t)r * 4 + 1] = e1 * inv;
            out_c2[(size_t)r * 4 + 2] = e2 * inv;
            out_c2[(size_t)r * 4 + 3] = e3 * inv;
        }
    }
}

// ---------------------------------------------------------------------------
// launch
// ---------------------------------------------------------------------------
extern "C" void kernel_launch(void* const* d_in, const int* in_sizes, int n_in,
                              void* d_out, int out_size)
{
    // metadata order: x, W1, W2, W3, m1, m2, m3, wo1, bo1, wo2, bo2, wo3, bo3
    const float* x   = (const float*)d_in[0];
    const float* W1  = (const float*)d_in[1];
    const float* W2  = (const float*)d_in[2];
    const float* W3  = (const float*)d_in[3];
    const float* wo1 = (const float*)d_in[7];
    const float* bo1 = (const float*)d_in[8];
    const float* wo2 = (const float*)d_in[9];
    const float* bo2 = (const float*)d_in[10];
    const float* wo3 = (const float*)d_in[11];
    const float* bo3 = (const float*)d_in[12];

    float* out = (float*)d_out;
    // output layout: reg [B,10], c1 [B,3], c2 [B,4], feat [B,744]
    float* out_reg  = out;
    float* out_c1   = out + (size_t)BATCH * 10;
    float* out_c2   = out + (size_t)BATCH * 13;
    float* out_feat = out + (size_t)BATCH * 17;

    constexpr int B_TILE = 16;                 // 8192 / 16 = 512 exactly
    static_assert(BATCH % B_TILE == 0, "B_TILE must divide BATCH");
    dim3 grid1((OUT_DIM + 127) / 128, BATCH / B_TILE);   // (6, 512)
    sparse_mlp_kernel<B_TILE><<<grid1, 128>>>(x, W1, W2, W3, out_feat);

    // head: 52 KB dynamic smem (> 48 KB static limit) — opt in once
    static bool attr_set = false;
    if (!attr_set) {
        cudaFuncSetAttribute(head_kernel,
                             cudaFuncAttributeMaxDynamicSharedMemorySize,
                             HEAD_SMEM);
        attr_set = true;
    }
    const int blocks2 = BATCH / 16;    // 2 rows/warp, 8 warps/block -> 512 blocks
    head_kernel<<<blocks2, 256, HEAD_SMEM>>>(out_feat, wo1, bo1, wo2, bo2,
                                             wo3, bo3, out_reg, out_c1, out_c2);
}